// round 13
// baseline (speedup 1.0000x reference)
#include <cuda_runtime.h>
#include <cstdint>

#define LL    320
#define DD    128
#define NBINS 32
#define EPSF  1e-8f

#define Z_ELEMS (LL*LL*DD)     // 13,107,200
#define P_ELEMS (3*LL*LL)      //    307,200
#define CD_ELEMS (LL*LL)       //    102,400
// output layout: [z | pxyz | cadistavg], all f32

// ---- cadistavg: 32x32 tiles, upper triangle, i-split x8, 2x2 microtile
#define NT2 10
#define C_TILES 55              // NT2*(NT2+1)/2
#define ICHUNKS 8
#define ISPAN  (LL/ICHUNKS)     // 40
#define C_BLOCKS (C_TILES*ICHUNKS)   // 440
#define CCH 8                   // i-rows staged per chunk
#define TILE_SZ 1024

// ---- z / p stream
#define ZB 3200
#define PB 300
#define ZUNROLL 4

#define GRID1 (C_BLOCKS + ZB + PB)   // 3940

__device__ float g_cd_part[ICHUNKS * C_TILES * TILE_SZ];   // 1.8 MB
__device__ int   g_tile_cnt[C_TILES];                      // zero-init; self-resetting

typedef unsigned long long u64;

__device__ __forceinline__ float fsqrt_approx(float x) {
    float y;
    asm("sqrt.approx.f32 %0, %1;" : "=f"(y) : "f"(x));
    return y;
}
__device__ __forceinline__ u64 pk2(float lo, float hi) {
    u64 r; asm("mov.b64 %0, {%1, %2};" : "=l"(r) : "f"(lo), "f"(hi)); return r;
}
__device__ __forceinline__ void upk2(u64 v, float& lo, float& hi) {
    asm("mov.b64 {%0, %1}, %2;" : "=f"(lo), "=f"(hi) : "l"(v));
}
__device__ __forceinline__ u64 add2(u64 a, u64 b) {
    u64 r; asm("add.rn.f32x2 %0, %1, %2;" : "=l"(r) : "l"(a), "l"(b)); return r;
}
__device__ __forceinline__ u64 fma2(u64 a, u64 b, u64 c) {
    u64 r; asm("fma.rn.f32x2 %0, %1, %2, %3;" : "=l"(r) : "l"(a), "l"(b), "l"(c)); return r;
}

// ============ single kernel: C partials (front) + z stream + pxyz ============
__global__ __launch_bounds__(256)
void fused1(const int* __restrict__ residx,
            const int* __restrict__ mask,        // bool as int32
            const float* __restrict__ emb,
            const float4* __restrict__ pair4,
            const float* __restrict__ predxyz,
            const float* __restrict__ maskdiag,
            float* __restrict__ out)
{
    const int blk = blockIdx.x;
    const int tid = threadIdx.x;

    if (blk < C_BLOCKS) {
        // K tile: component-split, column-permuted so {col, col+16} are an 8B pair
        __shared__ u64    sKx2[CCH][16];
        __shared__ u64    sKy2[CCH][16];
        __shared__ u64    sKz2[CCH][16];
        __shared__ float4 sJ[CCH][32];        // negated J values
        __shared__ int    sLast;

        const int tile = blk >> 3;            // 0..54
        const int chnk = blk & 7;             // i-chunk 0..7

        int a = 0, t = tile;                  // tile -> (a, b2), a <= b2
        while (t >= NT2 - a) { t -= NT2 - a; a++; }
        const int b2 = a + t;
        const int jt = a * 32;
        const int kt = b2 * 32;

        // staging roles: 128 threads/side, 2 adjacent cols each
        const int side  = tid >> 7;           // 0 = K, 1 = J
        const int rem   = tid & 127;
        const int sii   = rem >> 4;           // i-row within chunk
        const int cpair = (rem & 15) * 2;     // local col (even), covers +1 too
        const int scol  = (side ? jt : kt) + cpair;

        // compute role
        const int tx = tid & 15;
        const int ty = tid >> 4;

        const u64 eps2 = pk2(EPSF, EPSF);
        float v00 = 0.f, v01 = 0.f, v10 = 0.f, v11 = 0.f;

        const int ibeg = chnk * ISPAN;
        for (int i0 = ibeg; i0 < ibeg + ISPAN; i0 += CCH) {
            const int gi = i0 + sii;
            float2 px = *(const float2*)(predxyz + 0 * LL * LL + gi * LL + scol);
            float2 py = *(const float2*)(predxyz + 1 * LL * LL + gi * LL + scol);
            float2 pz = *(const float2*)(predxyz + 2 * LL * LL + gi * LL + scol);
            // diagonal zeroing (maskdiag == 1 - eye)
            if (gi == scol)     { px.x = 0.f; py.x = 0.f; pz.x = 0.f; }
            if (gi == scol + 1) { px.y = 0.f; py.y = 0.f; pz.y = 0.f; }

            __syncthreads();                  // previous chunk's compute done
            if (side == 0) {
                const int s0 = ((cpair & 15) << 1) | (cpair >> 4);
                const int s1 = (((cpair + 1) & 15) << 1) | ((cpair + 1) >> 4);
                ((float*)sKx2[sii])[s0] = px.x;  ((float*)sKx2[sii])[s1] = px.y;
                ((float*)sKy2[sii])[s0] = py.x;  ((float*)sKy2[sii])[s1] = py.y;
                ((float*)sKz2[sii])[s0] = pz.x;  ((float*)sKz2[sii])[s1] = pz.y;
            } else {
                sJ[sii][cpair]     = make_float4(-px.x, -py.x, -pz.x, 0.f);
                sJ[sii][cpair + 1] = make_float4(-px.y, -py.y, -pz.y, 0.f);
            }
            __syncthreads();                  // chunk staged

            #pragma unroll
            for (int ii = 0; ii < CCH; ii++) {
                const u64 kx2 = sKx2[ii][tx];
                const u64 ky2 = sKy2[ii][tx];
                const u64 kz2 = sKz2[ii][tx];
                const float4 ja = sJ[ii][ty];
                const float4 jb = sJ[ii][ty + 16];
                {
                    u64 dx = add2(kx2, pk2(ja.x, ja.x));
                    u64 dy = add2(ky2, pk2(ja.y, ja.y));
                    u64 dz = add2(kz2, pk2(ja.z, ja.z));
                    u64 s2 = fma2(dx, dx, fma2(dy, dy, fma2(dz, dz, eps2)));
                    float s0, s1; upk2(s2, s0, s1);
                    v00 += fsqrt_approx(s0);
                    v01 += fsqrt_approx(s1);
                }
                {
                    u64 dx = add2(kx2, pk2(jb.x, jb.x));
                    u64 dy = add2(ky2, pk2(jb.y, jb.y));
                    u64 dz = add2(kz2, pk2(jb.z, jb.z));
                    u64 s2 = fma2(dx, dx, fma2(dy, dy, fma2(dz, dz, eps2)));
                    float s0, s1; upk2(s2, s0, s1);
                    v10 += fsqrt_approx(s0);
                    v11 += fsqrt_approx(s1);
                }
            }
        }

        // compact partial (no mirror here)
        float* part = g_cd_part + (chnk * C_TILES + tile) * TILE_SZ;
        part[ ty       * 32 + tx     ] = v00;
        part[ ty       * 32 + tx + 16] = v01;
        part[(ty + 16) * 32 + tx     ] = v10;
        part[(ty + 16) * 32 + tx + 16] = v11;

        __threadfence();
        __syncthreads();
        if (tid == 0)
            sLast = (atomicAdd(&g_tile_cnt[tile], 1) == ICHUNKS - 1);
        __syncthreads();

        if (sLast) {
            __threadfence();                  // acquire other chunks' partials
            float* cd = out + Z_ELEMS + P_ELEMS;
            const float s = 1.0f / LL;
            #pragma unroll
            for (int q = 0; q < 4; q++) {
                const int jj = ty + (q >> 1) * 16;
                const int kk = tx + (q & 1) * 16;
                const float* p0 = g_cd_part + tile * TILE_SZ + jj * 32 + kk;
                float sum = 0.f;
                #pragma unroll
                for (int c = 0; c < ICHUNKS; c++)
                    sum += p0[c * (C_TILES * TILE_SZ)];
                sum *= s;
                cd[(jt + jj) * LL + (kt + kk)] = sum;
                if (a != b2)
                    cd[(kt + kk) * LL + (jt + jj)] = sum;   // symmetric mirror
            }
            if (tid == 0)
                g_tile_cnt[tile] = 0;         // reset for graph replay
        }

    } else if (blk < C_BLOCKS + ZB) {
        // ---- z = pair_feats + emb[idx]
        const float4* e4 = (const float4*)emb;
        float4* out4 = (float4*)out;
        const int stride = ZB * 256;
        int e = (blk - C_BLOCKS) * 256 + tid;
        #pragma unroll
        for (int k = 0; k < ZUNROLL; k++, e += stride) {
            const int p = e >> 5;
            const int s = e & 31;
            const int i = p / LL;
            const int j = p - i * LL;

            int m   = mask[i] & mask[j];
            int dif = residx[j] - residx[i];
            dif = min(max(dif, -NBINS), NBINS) + (NBINS + 1);
            const int idx = m ? dif : 0;

            float4 ev = e4[idx * (DD / 4) + s];
            float4 pv = pair4[e];
            out4[e] = make_float4(pv.x + ev.x, pv.y + ev.y,
                                  pv.z + ev.z, pv.w + ev.w);
        }
    } else {
        // ---- pxyz = predxyz * maskdiag
        const int e = (blk - C_BLOCKS - ZB) * 256 + tid;
        const float4* pr4 = (const float4*)predxyz;
        const float4* md4 = (const float4*)maskdiag;
        float4 pv = pr4[e];
        float4 mv = md4[e % (LL * LL / 4)];
        ((float4*)(out + Z_ELEMS))[e] =
            make_float4(pv.x * mv.x, pv.y * mv.y, pv.z * mv.z, pv.w * mv.w);
    }
}

extern "C" void kernel_launch(void* const* d_in, const int* in_sizes, int n_in,
                              void* d_out, int out_size) {
    const int*    residx   = (const int*)d_in[0];
    const int*    mask     = (const int*)d_in[1];
    const float*  emb      = (const float*)d_in[2];
    const float4* pair4    = (const float4*)d_in[3];
    const float*  predxyz  = (const float*)d_in[4];
    const float*  maskdiag = (const float*)d_in[5];
    float*        out      = (float*)d_out;

    fused1<<<GRID1, 256>>>(residx, mask, emb, pair4, predxyz, maskdiag, out);
}

// round 15
// speedup vs baseline: 1.0780x; 1.0780x over previous
#include <cuda_runtime.h>
#include <cstdint>

#define LL    320
#define DD    128
#define NBINS 32
#define EPSF  1e-8f

#define Z_ELEMS (LL*LL*DD)     // 13,107,200
#define P_ELEMS (3*LL*LL)      //    307,200
#define CD_ELEMS (LL*LL)       //    102,400
// output layout: [z | pxyz | cadistavg], all f32

// ---- cadistavg: 32x32 tiles, upper triangle, i-split x8, 2x2 microtile
#define NT2 10
#define C_TILES 55              // NT2*(NT2+1)/2
#define ICHUNKS 8
#define ISPAN  (LL/ICHUNKS)     // 40
#define C_BLOCKS (C_TILES*ICHUNKS)   // 440
#define CCH 8                   // i-rows staged per chunk
#define TILE_SZ 1024

// ---- z / p stream
#define ZB 3200
#define PB 300
#define ZUNROLL 4

#define GRID1 (C_BLOCKS + ZB + PB)   // 3940

__device__ float g_cd_part[ICHUNKS * C_TILES * TILE_SZ];   // 1.8 MB
__device__ int   g_tile_cnt[C_TILES];                      // zero-init; self-resetting

__device__ __forceinline__ float fsqrt_approx(float x) {
    float y;
    asm("sqrt.approx.f32 %0, %1;" : "=f"(y) : "f"(x));
    return y;
}

// dist via norm expansion: K.w = |k|^2 + eps, J = (-2jx,-2jy,-2jz, |j|^2)
// clamp against cancellation-induced negatives (j == k case) before sqrt
__device__ __forceinline__ float distNE(float4 k, float4 j) {
    float s = fmaf(k.x, j.x, fmaf(k.y, j.y, fmaf(k.z, j.z, k.w + j.w)));
    return fsqrt_approx(fmaxf(s, EPSF));
}

// ============ single kernel: C partials (front) + z stream + pxyz ============
__global__ __launch_bounds__(256)
void fused1(const int* __restrict__ residx,
            const int* __restrict__ mask,        // bool as int32
            const float* __restrict__ emb,
            const float4* __restrict__ pair4,
            const float* __restrict__ predxyz,
            const float* __restrict__ maskdiag,
            float* __restrict__ out)
{
    const int blk = blockIdx.x;
    const int tid = threadIdx.x;

    if (blk < C_BLOCKS) {
        // ---- cadistavg partial: 32x32 (j,k) tile over one i-chunk of 40
        __shared__ float4 sK[CCH][32];        // (kx,ky,kz, |k|^2+eps)
        __shared__ float4 sJ[CCH][32];        // (-2jx,-2jy,-2jz, |j|^2)
        __shared__ int    sLast;

        const int tile = blk >> 3;            // 0..54
        const int chnk = blk & 7;             // i-chunk 0..7

        int a = 0, t = tile;                  // tile -> (a, b2), a <= b2
        while (t >= NT2 - a) { t -= NT2 - a; a++; }
        const int b2 = a + t;
        const int jt = a * 32;
        const int kt = b2 * 32;

        // staging roles: 128 threads/side, 2 adjacent cols each
        const int side  = tid >> 7;           // 0 = K, 1 = J
        const int rem   = tid & 127;
        const int sii   = rem >> 4;           // i-row within chunk
        const int cpair = (rem & 15) * 2;     // local col (even)
        const int scol  = (side ? jt : kt) + cpair;

        // compute role: 2x2 microtile
        const int tx = tid & 15;
        const int ty = tid >> 4;

        float v00 = 0.f, v01 = 0.f, v10 = 0.f, v11 = 0.f;

        const int ibeg = chnk * ISPAN;
        for (int i0 = ibeg; i0 < ibeg + ISPAN; i0 += CCH) {
            const int gi = i0 + sii;
            float2 px = *(const float2*)(predxyz + 0 * LL * LL + gi * LL + scol);
            float2 py = *(const float2*)(predxyz + 1 * LL * LL + gi * LL + scol);
            float2 pz = *(const float2*)(predxyz + 2 * LL * LL + gi * LL + scol);
            // diagonal zeroing (maskdiag == 1 - eye)
            if (gi == scol)     { px.x = 0.f; py.x = 0.f; pz.x = 0.f; }
            if (gi == scol + 1) { px.y = 0.f; py.y = 0.f; pz.y = 0.f; }

            const float n0 = fmaf(px.x, px.x, fmaf(py.x, py.x, pz.x * pz.x));
            const float n1 = fmaf(px.y, px.y, fmaf(py.y, py.y, pz.y * pz.y));

            __syncthreads();                  // previous chunk's compute done
            if (side == 0) {
                sK[sii][cpair]     = make_float4(px.x, py.x, pz.x, n0 + EPSF);
                sK[sii][cpair + 1] = make_float4(px.y, py.y, pz.y, n1 + EPSF);
            } else {
                sJ[sii][cpair]     = make_float4(-2.f * px.x, -2.f * py.x, -2.f * pz.x, n0);
                sJ[sii][cpair + 1] = make_float4(-2.f * px.y, -2.f * py.y, -2.f * pz.y, n1);
            }
            __syncthreads();                  // chunk staged

            #pragma unroll
            for (int ii = 0; ii < CCH; ii++) {
                const float4 ka = sK[ii][tx];
                const float4 kb = sK[ii][tx + 16];
                const float4 ja = sJ[ii][ty];
                const float4 jb = sJ[ii][ty + 16];
                v00 += distNE(ka, ja);
                v01 += distNE(kb, ja);
                v10 += distNE(ka, jb);
                v11 += distNE(kb, jb);
            }
        }

        // compact partial (no mirror here)
        float* part = g_cd_part + (chnk * C_TILES + tile) * TILE_SZ;
        part[ ty       * 32 + tx     ] = v00;
        part[ ty       * 32 + tx + 16] = v01;
        part[(ty + 16) * 32 + tx     ] = v10;
        part[(ty + 16) * 32 + tx + 16] = v11;

        __threadfence();
        __syncthreads();
        if (tid == 0)
            sLast = (atomicAdd(&g_tile_cnt[tile], 1) == ICHUNKS - 1);
        __syncthreads();

        if (sLast) {
            __threadfence();                  // acquire other chunks' partials
            float* cd = out + Z_ELEMS + P_ELEMS;
            const float s = 1.0f / LL;
            #pragma unroll
            for (int q = 0; q < 4; q++) {
                const int jj = ty + (q >> 1) * 16;
                const int kk = tx + (q & 1) * 16;
                const float* p0 = g_cd_part + tile * TILE_SZ + jj * 32 + kk;
                float sum = 0.f;
                #pragma unroll
                for (int c = 0; c < ICHUNKS; c++)
                    sum += p0[c * (C_TILES * TILE_SZ)];
                sum *= s;
                cd[(jt + jj) * LL + (kt + kk)] = sum;
                if (a != b2)
                    cd[(kt + kk) * LL + (jt + jj)] = sum;   // symmetric mirror
            }
            if (tid == 0)
                g_tile_cnt[tile] = 0;         // reset for graph replay
        }

    } else if (blk < C_BLOCKS + ZB) {
        // ---- z = pair_feats + emb[idx]
        const float4* e4 = (const float4*)emb;
        float4* out4 = (float4*)out;
        const int stride = ZB * 256;
        int e = (blk - C_BLOCKS) * 256 + tid;
        #pragma unroll
        for (int k = 0; k < ZUNROLL; k++, e += stride) {
            const int p = e >> 5;
            const int s = e & 31;
            const int i = p / LL;
            const int j = p - i * LL;

            int m   = mask[i] & mask[j];
            int dif = residx[j] - residx[i];
            dif = min(max(dif, -NBINS), NBINS) + (NBINS + 1);
            const int idx = m ? dif : 0;

            float4 ev = e4[idx * (DD / 4) + s];
            float4 pv = pair4[e];
            out4[e] = make_float4(pv.x + ev.x, pv.y + ev.y,
                                  pv.z + ev.z, pv.w + ev.w);
        }
    } else {
        // ---- pxyz = predxyz * maskdiag
        const int e = (blk - C_BLOCKS - ZB) * 256 + tid;
        const float4* pr4 = (const float4*)predxyz;
        const float4* md4 = (const float4*)maskdiag;
        float4 pv = pr4[e];
        float4 mv = md4[e % (LL * LL / 4)];
        ((float4*)(out + Z_ELEMS))[e] =
            make_float4(pv.x * mv.x, pv.y * mv.y, pv.z * mv.z, pv.w * mv.w);
    }
}

extern "C" void kernel_launch(void* const* d_in, const int* in_sizes, int n_in,
                              void* d_out, int out_size) {
    const int*    residx   = (const int*)d_in[0];
    const int*    mask     = (const int*)d_in[1];
    const float*  emb      = (const float*)d_in[2];
    const float4* pair4    = (const float4*)d_in[3];
    const float*  predxyz  = (const float*)d_in[4];
    const float*  maskdiag = (const float*)d_in[5];
    float*        out      = (float*)d_out;

    fused1<<<GRID1, 256>>>(residx, mask, emb, pair4, predxyz, maskdiag, out);
}

// round 16
// speedup vs baseline: 1.0935x; 1.0144x over previous
#include <cuda_runtime.h>
#include <cstdint>

#define LL    320
#define DD    128
#define NBINS 32
#define EPSF  1e-8f

#define Z_ELEMS (LL*LL*DD)     // 13,107,200
#define P_ELEMS (3*LL*LL)      //    307,200
#define CD_ELEMS (LL*LL)       //    102,400
// output layout: [z | pxyz | cadistavg], all f32

// ---- cadistavg: 32x32 tiles, upper triangle, i-split x8, 2x2 microtile
#define NT2 10
#define C_TILES 55              // NT2*(NT2+1)/2
#define ICHUNKS 8
#define ISPAN  (LL/ICHUNKS)     // 40
#define C_BLOCKS (C_TILES*ICHUNKS)   // 440
#define CCH 8                   // i-rows staged per chunk
#define TILE_SZ 1024

// ---- z / p stream
#define ZB 3200
#define PB 300
#define ZUNROLL 4

__device__ float g_cd_part[ICHUNKS * C_TILES * TILE_SZ];   // 1.8 MB
__device__ int   g_tile_cnt[C_TILES];                      // zero-init; self-resetting

__device__ __forceinline__ float fsqrt_approx(float x) {
    float y;
    asm("sqrt.approx.f32 %0, %1;" : "=f"(y) : "f"(x));
    return y;
}

// dist via norm expansion: K.w = |k|^2 + eps, J = (-2jx,-2jy,-2jz, |j|^2)
// clamp against cancellation-induced negatives (j == k case) before sqrt
__device__ __forceinline__ float distNE(float4 k, float4 j) {
    float s = fmaf(k.x, j.x, fmaf(k.y, j.y, fmaf(k.z, j.z, k.w + j.w)));
    return fsqrt_approx(fmaxf(s, EPSF));
}

// ============ PRIMARY kernel: cadistavg partials + tail reduce ============
__global__ __launch_bounds__(256)
void c_kernel(const float* __restrict__ predxyz,
              float* __restrict__ out)
{
    // release the dependent zp_kernel as soon as all C blocks have started
    asm volatile("griddepcontrol.launch_dependents;" ::: "memory");

    __shared__ float4 sK[CCH][32];        // (kx,ky,kz, |k|^2+eps)
    __shared__ float4 sJ[CCH][32];        // (-2jx,-2jy,-2jz, |j|^2)
    __shared__ int    sLast;

    const int blk = blockIdx.x;
    const int tid = threadIdx.x;

    const int tile = blk >> 3;            // 0..54
    const int chnk = blk & 7;             // i-chunk 0..7

    int a = 0, t = tile;                  // tile -> (a, b2), a <= b2
    while (t >= NT2 - a) { t -= NT2 - a; a++; }
    const int b2 = a + t;
    const int jt = a * 32;
    const int kt = b2 * 32;

    // staging roles: 128 threads/side, 2 adjacent cols each
    const int side  = tid >> 7;           // 0 = K, 1 = J
    const int rem   = tid & 127;
    const int sii   = rem >> 4;           // i-row within chunk
    const int cpair = (rem & 15) * 2;     // local col (even)
    const int scol  = (side ? jt : kt) + cpair;

    // compute role: 2x2 microtile
    const int tx = tid & 15;
    const int ty = tid >> 4;

    float v00 = 0.f, v01 = 0.f, v10 = 0.f, v11 = 0.f;

    const int ibeg = chnk * ISPAN;
    for (int i0 = ibeg; i0 < ibeg + ISPAN; i0 += CCH) {
        const int gi = i0 + sii;
        float2 px = *(const float2*)(predxyz + 0 * LL * LL + gi * LL + scol);
        float2 py = *(const float2*)(predxyz + 1 * LL * LL + gi * LL + scol);
        float2 pz = *(const float2*)(predxyz + 2 * LL * LL + gi * LL + scol);
        // diagonal zeroing (maskdiag == 1 - eye)
        if (gi == scol)     { px.x = 0.f; py.x = 0.f; pz.x = 0.f; }
        if (gi == scol + 1) { px.y = 0.f; py.y = 0.f; pz.y = 0.f; }

        const float n0 = fmaf(px.x, px.x, fmaf(py.x, py.x, pz.x * pz.x));
        const float n1 = fmaf(px.y, px.y, fmaf(py.y, py.y, pz.y * pz.y));

        __syncthreads();                  // previous chunk's compute done
        if (side == 0) {
            sK[sii][cpair]     = make_float4(px.x, py.x, pz.x, n0 + EPSF);
            sK[sii][cpair + 1] = make_float4(px.y, py.y, pz.y, n1 + EPSF);
        } else {
            sJ[sii][cpair]     = make_float4(-2.f * px.x, -2.f * py.x, -2.f * pz.x, n0);
            sJ[sii][cpair + 1] = make_float4(-2.f * px.y, -2.f * py.y, -2.f * pz.y, n1);
        }
        __syncthreads();                  // chunk staged

        #pragma unroll
        for (int ii = 0; ii < CCH; ii++) {
            const float4 ka = sK[ii][tx];
            const float4 kb = sK[ii][tx + 16];
            const float4 ja = sJ[ii][ty];
            const float4 jb = sJ[ii][ty + 16];
            v00 += distNE(ka, ja);
            v01 += distNE(kb, ja);
            v10 += distNE(ka, jb);
            v11 += distNE(kb, jb);
        }
    }

    // compact partial (no mirror here)
    float* part = g_cd_part + (chnk * C_TILES + tile) * TILE_SZ;
    part[ ty       * 32 + tx     ] = v00;
    part[ ty       * 32 + tx + 16] = v01;
    part[(ty + 16) * 32 + tx     ] = v10;
    part[(ty + 16) * 32 + tx + 16] = v11;

    __threadfence();
    __syncthreads();
    if (tid == 0)
        sLast = (atomicAdd(&g_tile_cnt[tile], 1) == ICHUNKS - 1);
    __syncthreads();

    if (sLast) {
        __threadfence();                  // acquire other chunks' partials
        float* cd = out + Z_ELEMS + P_ELEMS;
        const float s = 1.0f / LL;
        #pragma unroll
        for (int q = 0; q < 4; q++) {
            const int jj = ty + (q >> 1) * 16;
            const int kk = tx + (q & 1) * 16;
            const float* p0 = g_cd_part + tile * TILE_SZ + jj * 32 + kk;
            float sum = 0.f;
            #pragma unroll
            for (int c = 0; c < ICHUNKS; c++)
                sum += p0[c * (C_TILES * TILE_SZ)];
            sum *= s;
            cd[(jt + jj) * LL + (kt + kk)] = sum;
            if (a != b2)
                cd[(kt + kk) * LL + (jt + jj)] = sum;   // symmetric mirror
        }
        if (tid == 0)
            g_tile_cnt[tile] = 0;         // reset for graph replay
    }
}

// ============ SECONDARY kernel (PDL): z = pair_feats + emb[idx], + pxyz ============
__global__ __launch_bounds__(256)
void zp_kernel(const int* __restrict__ residx,
               const int* __restrict__ mask,      // bool as int32
               const float* __restrict__ emb,
               const float4* __restrict__ pair4,
               const float4* __restrict__ pred4,
               const float4* __restrict__ md4,
               float* __restrict__ out)
{
    // no griddepcontrol.wait: this kernel never reads c_kernel's writes
    const int blk = blockIdx.x;
    const int tid = threadIdx.x;

    if (blk < ZB) {
        const float4* e4 = (const float4*)emb;
        float4* out4 = (float4*)out;
        const int stride = ZB * 256;
        int e = blk * 256 + tid;                 // float4 index into z
        #pragma unroll
        for (int k = 0; k < ZUNROLL; k++, e += stride) {
            const int p = e >> 5;                // pair index (32 f4 per pair)
            const int s = e & 31;                // f4 slot within D=128
            const int i = p / LL;
            const int j = p - i * LL;

            int m   = mask[i] & mask[j];
            int dif = residx[j] - residx[i];
            dif = min(max(dif, -NBINS), NBINS) + (NBINS + 1);
            const int idx = m ? dif : 0;

            float4 ev = e4[idx * (DD / 4) + s];
            float4 pv = pair4[e];
            out4[e] = make_float4(pv.x + ev.x, pv.y + ev.y,
                                  pv.z + ev.z, pv.w + ev.w);
        }
    } else {
        // pxyz = predxyz * maskdiag
        const int e = (blk - ZB) * 256 + tid;    // < 76800
        float4 pv = pred4[e];
        float4 mv = md4[e % (LL * LL / 4)];
        ((float4*)(out + Z_ELEMS))[e] =
            make_float4(pv.x * mv.x, pv.y * mv.y, pv.z * mv.z, pv.w * mv.w);
    }
}

extern "C" void kernel_launch(void* const* d_in, const int* in_sizes, int n_in,
                              void* d_out, int out_size) {
    const int*    residx   = (const int*)d_in[0];
    const int*    mask     = (const int*)d_in[1];
    const float*  emb      = (const float*)d_in[2];
    const float4* pair4    = (const float4*)d_in[3];
    const float*  predxyz  = (const float*)d_in[4];
    const float*  maskdiag = (const float*)d_in[5];
    float*        out      = (float*)d_out;

    // primary: C (all 440 blocks resident immediately; releases dependents at entry)
    {
        cudaLaunchConfig_t cfg = {};
        cfg.gridDim  = dim3(C_BLOCKS);
        cfg.blockDim = dim3(256);
        cudaLaunchKernelEx(&cfg, c_kernel, predxyz, out);
    }
    // secondary: Z+P with programmatic dependent launch -> overlaps with C
    {
        cudaLaunchAttribute attr[1];
        attr[0].id = cudaLaunchAttributeProgrammaticStreamSerialization;
        attr[0].val.programmaticStreamSerializationAllowed = 1;
        cudaLaunchConfig_t cfg = {};
        cfg.gridDim  = dim3(ZB + PB);
        cfg.blockDim = dim3(256);
        cfg.attrs    = attr;
        cfg.numAttrs = 1;
        cudaLaunchKernelEx(&cfg, zp_kernel, residx, mask, emb, pair4,
                           (const float4*)predxyz, (const float4*)maskdiag, out);
    }
}